// round 6
// baseline (speedup 1.0000x reference)
#include <cuda_runtime.h>

// out[r] = (sum over 1024 elems of row r of x) * (sum of coeffs)
// x: (16, 4096, 1024) fp32 -> 65536 rows of 1024
// coeffs: (10, 1) fp32
//
// Persistent grid-stride version: grid sized to exactly one full wave
// (148 SMs x 8 blocks/SM = 1184 blocks of 256 threads). Each warp
// processes rows r, r+nwarps, ... Streaming loads (__ldcs) to minimize
// L2 allocation on zero-reuse data.

__global__ __launch_bounds__(256) void spline_rowsum_persistent(
    const float* __restrict__ x,
    const float* __restrict__ coeffs,
    int n_coeffs,
    float* __restrict__ out,
    int nrows)
{
    const int lane   = threadIdx.x & 31;
    const int gwarp0 = (blockIdx.x * blockDim.x + threadIdx.x) >> 5;
    const int nwarps = (gridDim.x * blockDim.x) >> 5;

    // coeff sum (tiny, L2/L1 resident after first warp)
    float c = 0.0f;
    for (int i = 0; i < n_coeffs; i++) c += coeffs[i];

    for (int r = gwarp0; r < nrows; r += nwarps) {
        const float4* row = reinterpret_cast<const float4*>(x) + (size_t)r * 256;

        // 8 independent 16B streaming loads per lane (MLP=8)
        float4 v0 = __ldcs(row + lane + 0 * 32);
        float4 v1 = __ldcs(row + lane + 1 * 32);
        float4 v2 = __ldcs(row + lane + 2 * 32);
        float4 v3 = __ldcs(row + lane + 3 * 32);
        float4 v4 = __ldcs(row + lane + 4 * 32);
        float4 v5 = __ldcs(row + lane + 5 * 32);
        float4 v6 = __ldcs(row + lane + 6 * 32);
        float4 v7 = __ldcs(row + lane + 7 * 32);

        float s01 = (v0.x + v0.y) + (v0.z + v0.w) + (v1.x + v1.y) + (v1.z + v1.w);
        float s23 = (v2.x + v2.y) + (v2.z + v2.w) + (v3.x + v3.y) + (v3.z + v3.w);
        float s45 = (v4.x + v4.y) + (v4.z + v4.w) + (v5.x + v5.y) + (v5.z + v5.w);
        float s67 = (v6.x + v6.y) + (v6.z + v6.w) + (v7.x + v7.y) + (v7.z + v7.w);
        float s = (s01 + s23) + (s45 + s67);

        // butterfly warp reduction
#pragma unroll
        for (int off = 16; off; off >>= 1)
            s += __shfl_xor_sync(0xFFFFFFFFu, s, off);

        if (lane == 0)
            out[r] = s * c;
    }
}

extern "C" void kernel_launch(void* const* d_in, const int* in_sizes, int n_in,
                              void* d_out, int out_size)
{
    const float* x      = (const float*)d_in[0];
    const float* coeffs = (const float*)d_in[1];
    float* out          = (float*)d_out;

    int nrows    = in_sizes[0] / 1024;   // 65536
    int n_coeffs = in_sizes[1];          // 10

    // One full wave: 148 SMs * 8 blocks/SM (256 thr, 31 regs -> occ 8)
    int blocks = 148 * 8;
    spline_rowsum_persistent<<<blocks, 256>>>(x, coeffs, n_coeffs, out, nrows);
}